// round 13
// baseline (speedup 1.0000x reference)
#include <cuda_runtime.h>
#include <cuda_fp16.h>
#include <cstdint>

#define SEQ 512
#define BATCH 64
#define HID 1024
#define G4 4096
#define BH (BATCH*HID)
#define BG (BATCH*G4)
#define YSZ (SEQ*BH)
#define HOFF YSZ
#define COFF (YSZ+2*BH)
#define NCTA 128

__device__ __align__(16) float  g_gi[SEQ*BG];     // input projections (fp32)
__device__ __align__(16) __half g_xh[SEQ*BH];     // x in fp16
__device__ __align__(16) __half g_h16[SEQ*BH];    // h stream fp16 (per layer)
__device__ __align__(16) __half g_wh[2*G4*HID];   // W_ih fp16, both layers
__device__ int g_flags[NCTA*32];                  // per-CTA progress flags

// ---------------- helpers ---------------------------------------------------
__device__ __forceinline__ uint32_t smem_u32(const void* p) {
    uint32_t a;
    asm("{ .reg .u64 t; cvta.to.shared.u64 t, %1; cvt.u32.u64 %0, t; }"
        : "=r"(a) : "l"(p));
    return a;
}
#define SW128(x) ((x) ^ (((x) >> 3) & 0x70))

__device__ __forceinline__ void cp_async16(uint32_t dst, const void* src) {
    asm volatile("cp.async.cg.shared.global [%0], [%1], 16;" :: "r"(dst), "l"(src));
}
__device__ __forceinline__ void cp_commit() {
    asm volatile("cp.async.commit_group;");
}
template <int N> __device__ __forceinline__ void cp_wait() {
    asm volatile("cp.async.wait_group %0;" :: "n"(N));
}
__device__ __forceinline__ void sts128(uint32_t a, uint32_t x, uint32_t y,
                                       uint32_t z, uint32_t w) {
    asm volatile("st.shared.v4.b32 [%0], {%1,%2,%3,%4};"
                 :: "r"(a), "r"(x), "r"(y), "r"(z), "r"(w) : "memory");
}
__device__ __forceinline__ void ldm4(uint32_t* r, uint32_t a) {
    asm volatile("ldmatrix.sync.aligned.m8n8.x4.shared.b16 {%0,%1,%2,%3}, [%4];"
                 : "=r"(r[0]), "=r"(r[1]), "=r"(r[2]), "=r"(r[3]) : "r"(a));
}
__device__ __forceinline__ void ldm2(uint32_t* r, uint32_t a) {
    asm volatile("ldmatrix.sync.aligned.m8n8.x2.shared.b16 {%0,%1}, [%2];"
                 : "=r"(r[0]), "=r"(r[1]) : "r"(a));
}
__device__ __forceinline__ void mma16816(float* c, const uint32_t* a,
                                         const uint32_t* b) {
    asm volatile(
        "mma.sync.aligned.m16n8k16.row.col.f32.f16.f16.f32 "
        "{%0,%1,%2,%3}, {%4,%5,%6,%7}, {%8,%9}, {%0,%1,%2,%3};"
        : "+f"(c[0]), "+f"(c[1]), "+f"(c[2]), "+f"(c[3])
        : "r"(a[0]), "r"(a[1]), "r"(a[2]), "r"(a[3]), "r"(b[0]), "r"(b[1]));
}
__device__ __forceinline__ void mbar_init(uint32_t a, uint32_t c) {
    asm volatile("mbarrier.init.shared.b64 [%0], %1;" :: "r"(a), "r"(c) : "memory");
}
__device__ __forceinline__ void mbar_arrive(uint32_t a) {
    asm volatile("mbarrier.arrive.shared.b64 _, [%0];" :: "r"(a) : "memory");
}
__device__ __forceinline__ void mbar_wait(uint32_t a, uint32_t par) {
    asm volatile(
        "{\n\t.reg .pred P;\n\tL%=:\n\t"
        "mbarrier.try_wait.parity.acquire.cta.shared::cta.b64 P, [%0], %1, 0x989680;\n\t"
        "@!P bra L%=;\n\t}" :: "r"(a), "r"(par) : "memory");
}
__device__ __forceinline__ void cp_async_mbar(uint32_t a) {
    asm volatile("cp.async.mbarrier.arrive.noinc.shared.b64 [%0];"
                 :: "r"(a) : "memory");
}
__device__ __forceinline__ float sigm(float x)   { return 1.f / (1.f + __expf(-x)); }
__device__ __forceinline__ float tanh_f(float x) { return 1.f - 2.f / (__expf(2.f*x) + 1.f); }
__device__ __forceinline__ uint32_t h2u(__half2 h) { return *(uint32_t*)&h; }

// ---------------------------------------------------------------------------
__global__ void reset_flags_kernel() {
    if (threadIdx.x < NCTA) g_flags[threadIdx.x * 32] = 0;
}

__global__ void f2h_kernel(const float* __restrict__ in, __half* __restrict__ o,
                           int n8) {
    int i = blockIdx.x * 256 + threadIdx.x;
    if (i < n8) {
        float4 a = ((const float4*)in)[2*i];
        float4 b = ((const float4*)in)[2*i+1];
        uint4 v;
        v.x = h2u(__floats2half2_rn(a.x, a.y));
        v.y = h2u(__floats2half2_rn(a.z, a.w));
        v.z = h2u(__floats2half2_rn(b.x, b.y));
        v.w = h2u(__floats2half2_rn(b.z, b.w));
        ((uint4*)o)[i] = v;
    }
}

// ---------------------------------------------------------------------------
// gi = A(fp16)@B(fp16)^T + b1 + b2.  (R12 GEMM, measured equal to R9)
#define GH_SMEM (1024 + 98304)
__global__ __launch_bounds__(256, 2) void gemm_h(
    const __half* __restrict__ A, const __half* __restrict__ B,
    const float* __restrict__ b1, const float* __restrict__ b2,
    float* __restrict__ C)
{
    extern __shared__ char sm_[];
    const uint32_t base = (smem_u32(sm_) + 1023) & ~1023u;
    const int tid = threadIdx.x, wid = tid >> 5, lane = tid & 31;
    const int nb = blockIdx.x * 128, mb = blockIdx.y * 128;
    const int wm = wid >> 2, wn = wid & 3;

    const int lrow = tid >> 1;
    const int ls0  = (tid & 1) * 4;
    const char* asrc0 = (const char*)(A + (size_t)(mb + lrow) * 1024);
    const char* bsrc0 = (const char*)(B + (size_t)(nb + lrow) * 1024);

    float acc[4][4][4];
#pragma unroll
    for (int i = 0; i < 4; i++)
#pragma unroll
        for (int j = 0; j < 4; j++)
#pragma unroll
            for (int q = 0; q < 4; q++) acc[i][j][q] = 0.f;

    const int lr = lane & 7, lg = lane >> 3;
    const int arow = lr + ((lg & 1) << 3), aksel = lg >> 1;
    const int brow = lr + ((lg >> 1) << 3), bksel = lg & 1;

#pragma unroll
    for (int p = 0; p < 2; p++) {
        uint32_t ab = base + p * 32768;
#pragma unroll
        for (int i = 0; i < 4; i++) {
            int s = ls0 + i;
            cp_async16(ab + SW128(lrow * 128 + s * 16), asrc0 + p * 128 + s * 16);
            cp_async16(ab + 16384 + SW128(lrow * 128 + s * 16),
                       bsrc0 + p * 128 + s * 16);
        }
        cp_commit();
    }

    for (int c = 0; c < 16; c++) {
        if (c + 2 < 16) {
            uint32_t ab = base + ((c + 2) % 3) * 32768;
#pragma unroll
            for (int i = 0; i < 4; i++) {
                int s = ls0 + i;
                cp_async16(ab + SW128(lrow * 128 + s * 16),
                           asrc0 + (c + 2) * 128 + s * 16);
                cp_async16(ab + 16384 + SW128(lrow * 128 + s * 16),
                           bsrc0 + (c + 2) * 128 + s * 16);
            }
        }
        cp_commit();
        cp_wait<2>();
        __syncthreads();
        uint32_t ab = base + (c % 3) * 32768;
        uint32_t bb = ab + 16384;
#pragma unroll
        for (int ks = 0; ks < 4; ks++) {
            uint32_t afr[4][4], bfr[2][4];
#pragma unroll
            for (int mf = 0; mf < 4; mf++)
                ldm4(afr[mf], ab + SW128((wm * 64 + mf * 16 + arow) * 128
                                         + (ks * 2 + aksel) * 16));
#pragma unroll
            for (int bh = 0; bh < 2; bh++)
                ldm4(bfr[bh], bb + SW128((wn * 32 + bh * 16 + brow) * 128
                                         + (ks * 2 + bksel) * 16));
#pragma unroll
            for (int mf = 0; mf < 4; mf++)
#pragma unroll
                for (int nf = 0; nf < 4; nf++)
                    mma16816(acc[mf][nf], afr[mf], &bfr[nf >> 1][(nf & 1) * 2]);
        }
        __syncthreads();
    }

#pragma unroll
    for (int mf = 0; mf < 4; mf++) {
#pragma unroll
        for (int nf = 0; nf < 4; nf++) {
            int m = mb + wm * 64 + mf * 16 + (lane >> 2);
            int n = nb + wn * 32 + nf * 8 + 2 * (lane & 3);
            float bs0 = b1[n] + b2[n], bs1 = b1[n + 1] + b2[n + 1];
            float* cp0 = C + (size_t)m * 4096 + n;
            float* cp1 = cp0 + 8 * 4096;
            *(float2*)cp0 = make_float2(acc[mf][nf][0] + bs0, acc[mf][nf][1] + bs1);
            *(float2*)cp1 = make_float2(acc[mf][nf][2] + bs0, acc[mf][nf][3] + bs1);
        }
    }
}

// ---------------------------------------------------------------------------
// Warp-specialized dataflow recurrence. 288 threads: warps 0-7 compute,
// warp 8 = DMA (flag polls + cp.async + mbarrier signal). Per-group full/cons
// mbarriers replace all GEMM-loop syncthreads. R9 flag dynamics retained.
// SMEM: W 128K | A 64K (16x4KB) | Gs 8448B | 8 mbarriers.
#define R_SMEM (1024 + 131072 + 65536 + 8448 + 64)
__global__ __launch_bounds__(288) void lstm_df(
    const float* __restrict__ Whh, const float* __restrict__ gi,
    __half* __restrict__ h16, float* __restrict__ yout,
    float* __restrict__ out, int layer, int full)
{
    extern __shared__ char sm_[];
    const uint32_t base = (smem_u32(sm_) + 1023) & ~1023u;
    const uint32_t Wb = base, Ab = base + 131072, GsB = base + 196608;
    const uint32_t MB = base + 196608 + 8448;      // full[4] @+0, cons[4] @+32
    float* Gs = (float*)(sm_ + (GsB - smem_u32(sm_)));
    const int tid = threadIdx.x, wid = tid >> 5, lane = tid & 31;
    const int jb = blockIdx.x;
    const int cg = jb >> 1;            // col-group 0..63
    const int bs = jb & 1;             // batch half 0..1

    if (tid == 0) {
#pragma unroll
        for (int g = 0; g < 4; g++) {
            mbar_init(MB + g * 8, 32);        // full[g]: 32 DMA-lane arrivals
            mbar_init(MB + 32 + g * 8, 8);    // cons[g]: 8 compute-warp arrivals
        }
    }
    // ---- W_hh slice -> fp16 SMEM (compute threads only) ----
    if (tid < 256) {
#pragma unroll 2
        for (int it = 0; it < 32; it++) {
            int idx = tid + it * 256;
            int lc = idx >> 7;
            int k8 = (idx & 127) * 8;
            int grow = ((lc >> 4) << 10) + cg * 16 + (lc & 15);
            const float* wp = Whh + (size_t)grow * 1024 + k8;
            float4 u = *(const float4*)wp;
            float4 v = *(const float4*)(wp + 4);
            sts128(Wb + (k8 >> 6) * 8192 + SW128(lc * 128 + (k8 & 63) * 2),
                   h2u(__floats2half2_rn(u.x, u.y)), h2u(__floats2half2_rn(u.z, u.w)),
                   h2u(__floats2half2_rn(v.x, v.y)), h2u(__floats2half2_rn(v.z, v.w)));
        }
    }
    __syncthreads();

    if (wid == 8) {
        // ================= DMA warp =================
        for (int t = 1; t < SEQ; t++) {
            const char* hp = (const char*)(h16 + (size_t)(t - 1) * BH);
#pragma unroll
            for (int g = 0; g < 4; g++) {
                if (t >= 2) mbar_wait(MB + 32 + g * 8, (t - 2) & 1);
                if (lane < 16) {
                    const int* fp = (const int*)&g_flags[((g * 16 + lane) * 2 + bs) * 32];
                    int v;
                    do {
                        asm volatile("ld.acquire.gpu.global.b32 %0, [%1];"
                                     : "=r"(v) : "l"(fp));
                    } while (v < t);
                }
                __syncwarp();
#pragma unroll 4
                for (int i = 0; i < 32; i++) {
                    int idx = lane + i * 32;           // 0..1023
                    int c = g * 4 + (idx >> 8);
                    int row = (idx >> 3) & 31;
                    int seg = idx & 7;
                    cp_async16(Ab + c * 4096 + SW128(row * 128 + seg * 16),
                               hp + (size_t)(bs * 32 + row) * 2048 + c * 128 + seg * 16);
                }
                cp_async_mbar(MB + g * 8);
            }
        }
        return;
    }

    // ================= compute warps (tid < 256) =================
    const int wn = wid;
    const int n0 = wn * 8;
    const int lr = lane & 7, lg = lane >> 3;
    const int arow = lr + ((lg & 1) << 3), aksel = lg >> 1;
    const int bnr = lane & 7, bksel = (lane >> 3) & 1;

    const int bl = tid >> 3;
    const int jl0 = (tid & 7) * 2;
    float creg2[2] = {0.f, 0.f};

    for (int t = 0; t < SEQ; t++) {
        const float* gp = gi + (size_t)t * BG
                        + (size_t)(bs * 32 + bl) * 4096 + cg * 16 + jl0;
        float2 ggv[4];
#pragma unroll
        for (int g = 0; g < 4; g++) ggv[g] = *(const float2*)(gp + (g << 10));

        if (t > 0) {
            float acc[2][4];
#pragma unroll
            for (int f = 0; f < 2; f++)
#pragma unroll
                for (int q = 0; q < 4; q++) acc[f][q] = 0.f;

#pragma unroll
            for (int g = 0; g < 4; g++) {
                mbar_wait(MB + g * 8, (t - 1) & 1);
#pragma unroll
                for (int cc = 0; cc < 4; cc++) {
                    int c = g * 4 + cc;
                    uint32_t wbase = Wb + c * 8192, abase = Ab + c * 4096;
#pragma unroll
                    for (int ks = 0; ks < 4; ks++) {
                        uint32_t af0[4], af1[4], bf[2];
                        ldm4(af0, abase + SW128(arow * 128 + (ks * 2 + aksel) * 16));
                        ldm4(af1, abase + SW128((16 + arow) * 128 + (ks * 2 + aksel) * 16));
                        ldm2(bf, wbase + SW128((n0 + bnr) * 128 + (ks * 2 + bksel) * 16));
                        mma16816(acc[0], af0, bf);
                        mma16816(acc[1], af1, bf);
                    }
                }
                if (lane == 0) mbar_arrive(MB + 32 + g * 8);
            }
            // gate exchange: Gs[lc][b] (stride 33)
            {
                int bf0 = lane >> 2;
                int lc = n0 + 2 * (lane & 3);
#pragma unroll
                for (int f = 0; f < 2; f++) {
                    int b = f * 16 + bf0;
                    Gs[lc * 33 + b]            = acc[f][0];
                    Gs[(lc + 1) * 33 + b]      = acc[f][1];
                    Gs[lc * 33 + b + 8]        = acc[f][2];
                    Gs[(lc + 1) * 33 + b + 8]  = acc[f][3];
                }
            }
            asm volatile("bar.sync 1, 256;" ::: "memory");
        }

        // ---- cell update: 256 threads x 2 cells ----
        float hv2[2];
#pragma unroll
        for (int e = 0; e < 2; e++) {
            int jl = jl0 + e;
            float i_g = (e ? ggv[0].y : ggv[0].x);
            float f_g = (e ? ggv[1].y : ggv[1].x);
            float g_g = (e ? ggv[2].y : ggv[2].x);
            float o_g = (e ? ggv[3].y : ggv[3].x);
            if (t > 0) {
                i_g += Gs[(0 * 16 + jl) * 33 + bl];
                f_g += Gs[(1 * 16 + jl) * 33 + bl];
                g_g += Gs[(2 * 16 + jl) * 33 + bl];
                o_g += Gs[(3 * 16 + jl) * 33 + bl];
            }
            float cn = sigm(f_g) * creg2[e] + sigm(i_g) * tanh_f(g_g);
            creg2[e] = cn;
            hv2[e] = sigm(o_g) * tanh_f(cn);
        }
        size_t off = (size_t)t * BH + (size_t)(bs * 32 + bl) * 1024 + cg * 16 + jl0;
        *(uint32_t*)(h16 + off) = h2u(__floats2half2_rn(hv2[0], hv2[1]));
        __threadfence();
        asm volatile("bar.sync 1, 256;" ::: "memory");
        if (tid == 0 && t < SEQ - 1)
            asm volatile("st.release.gpu.global.b32 [%0], %1;"
                         :: "l"(&g_flags[jb * 32]), "r"(t + 1) : "memory");
        if (yout) {
            *(float2*)(yout + off) = make_float2(hv2[0], hv2[1]);
        }
        if (t == SEQ - 1 && full) {
            size_t tail = (size_t)layer * BH
                        + (size_t)(bs * 32 + bl) * 1024 + cg * 16 + jl0;
            *(float2*)(out + HOFF + tail) = make_float2(hv2[0], hv2[1]);
            *(float2*)(out + COFF + tail) = make_float2(creg2[0], creg2[1]);
        }
    }
}

// ---------------------------------------------------------------------------
extern "C" void kernel_launch(void* const* d_in, const int* in_sizes, int n_in,
                              void* d_out, int out_size)
{
    const float* x    = (const float*)d_in[0];
    const float* wih0 = (const float*)d_in[1];
    const float* whh0 = (const float*)d_in[2];
    const float* bih0 = (const float*)d_in[3];
    const float* bhh0 = (const float*)d_in[4];
    const float* wih1 = (const float*)d_in[5];
    const float* whh1 = (const float*)d_in[6];
    const float* bih1 = (const float*)d_in[7];
    const float* bhh1 = (const float*)d_in[8];
    float* out = (float*)d_out;

    float *gi; __half *xh, *h16, *wh;
    cudaGetSymbolAddress((void**)&gi,  g_gi);
    cudaGetSymbolAddress((void**)&xh,  g_xh);
    cudaGetSymbolAddress((void**)&h16, g_h16);
    cudaGetSymbolAddress((void**)&wh,  g_wh);

    cudaFuncSetAttribute(gemm_h,  cudaFuncAttributeMaxDynamicSharedMemorySize, GH_SMEM);
    cudaFuncSetAttribute(lstm_df, cudaFuncAttributeMaxDynamicSharedMemorySize, R_SMEM);

    const int full = (out_size >= (int)(YSZ + 4 * BH)) ? 1 : 0;
    dim3 gg(32, 256);
    const int WN8 = G4 * HID / 8;

    f2h_kernel<<<(SEQ * BH / 8 + 255) / 256, 256>>>(x, xh, SEQ * BH / 8);
    f2h_kernel<<<(WN8 + 255) / 256, 256>>>(wih0, wh, WN8);
    f2h_kernel<<<(WN8 + 255) / 256, 256>>>(wih1, wh + (size_t)G4 * HID, WN8);

    // Layer 0
    reset_flags_kernel<<<1, 128>>>();
    gemm_h<<<gg, 256, GH_SMEM>>>(xh, wh, bih0, bhh0, gi);
    lstm_df<<<NCTA, 288, R_SMEM>>>(whh0, gi, h16, (float*)0, out, 0, full);
    // Layer 1 (GEMM A operand = layer-0 h16 stream)
    gemm_h<<<gg, 256, GH_SMEM>>>(h16, wh + (size_t)G4 * HID, bih1, bhh1, gi);
    reset_flags_kernel<<<1, 128>>>();
    lstm_df<<<NCTA, 288, R_SMEM>>>(whh1, gi, h16, out, out, 1, full);
}

// round 15
// speedup vs baseline: 1.2917x; 1.2917x over previous
#include <cuda_runtime.h>
#include <cuda_fp16.h>
#include <cstdint>

#define SEQ 512
#define BATCH 64
#define HID 1024
#define G4 4096
#define BH (BATCH*HID)
#define BG (BATCH*G4)
#define YSZ (SEQ*BH)
#define HOFF YSZ
#define COFF (YSZ+2*BH)
#define NCTA 128

__device__ __align__(16) float  g_gi[SEQ*BG];     // layer-0 input projections
__device__ __align__(16) __half g_xh[SEQ*BH];     // x fp16
__device__ __align__(16) __half g_h16[SEQ*BH];    // y0 stream fp16
__device__ __align__(16) __half g_h1[SEQ*BH];     // h1 stream fp16
__device__ __align__(16) __half g_wh[2*G4*HID];   // wih0 | wih1 fp16
__device__ __align__(16) __half g_whh1h[G4*HID];  // whh1 fp16
__device__ int g_flags[2*NCTA*32];                // f0 [0..127], f1 [128..255]

// ---------------- helpers ---------------------------------------------------
__device__ __forceinline__ uint32_t smem_u32(const void* p) {
    uint32_t a;
    asm("{ .reg .u64 t; cvta.to.shared.u64 t, %1; cvt.u32.u64 %0, t; }"
        : "=r"(a) : "l"(p));
    return a;
}
#define SW128(x) ((x) ^ (((x) >> 3) & 0x70))

__device__ __forceinline__ void cp_async16(uint32_t dst, const void* src) {
    asm volatile("cp.async.cg.shared.global [%0], [%1], 16;" :: "r"(dst), "l"(src));
}
__device__ __forceinline__ void cp_commit() {
    asm volatile("cp.async.commit_group;");
}
template <int N> __device__ __forceinline__ void cp_wait() {
    asm volatile("cp.async.wait_group %0;" :: "n"(N));
}
__device__ __forceinline__ void sts128(uint32_t a, uint32_t x, uint32_t y,
                                       uint32_t z, uint32_t w) {
    asm volatile("st.shared.v4.b32 [%0], {%1,%2,%3,%4};"
                 :: "r"(a), "r"(x), "r"(y), "r"(z), "r"(w) : "memory");
}
__device__ __forceinline__ void ldm4(uint32_t* r, uint32_t a) {
    asm volatile("ldmatrix.sync.aligned.m8n8.x4.shared.b16 {%0,%1,%2,%3}, [%4];"
                 : "=r"(r[0]), "=r"(r[1]), "=r"(r[2]), "=r"(r[3]) : "r"(a));
}
__device__ __forceinline__ void ldm2(uint32_t* r, uint32_t a) {
    asm volatile("ldmatrix.sync.aligned.m8n8.x2.shared.b16 {%0,%1}, [%2];"
                 : "=r"(r[0]), "=r"(r[1]) : "r"(a));
}
__device__ __forceinline__ void mma16816(float* c, const uint32_t* a,
                                         const uint32_t* b) {
    asm volatile(
        "mma.sync.aligned.m16n8k16.row.col.f32.f16.f16.f32 "
        "{%0,%1,%2,%3}, {%4,%5,%6,%7}, {%8,%9}, {%0,%1,%2,%3};"
        : "+f"(c[0]), "+f"(c[1]), "+f"(c[2]), "+f"(c[3])
        : "r"(a[0]), "r"(a[1]), "r"(a[2]), "r"(a[3]), "r"(b[0]), "r"(b[1]));
}
__device__ __forceinline__ void poll_ge(const int* fp, int t) {
    int v;
    do {
        asm volatile("ld.acquire.gpu.global.b32 %0, [%1];" : "=r"(v) : "l"(fp));
    } while (v < t);
}
__device__ __forceinline__ float sigm(float x)   { return 1.f / (1.f + __expf(-x)); }
__device__ __forceinline__ float tanh_f(float x) { return 1.f - 2.f / (__expf(2.f*x) + 1.f); }
__device__ __forceinline__ uint32_t h2u(__half2 h) { return *(uint32_t*)&h; }

// ---------------------------------------------------------------------------
__global__ void reset_flags_kernel() {
    if (threadIdx.x < 2 * NCTA) g_flags[threadIdx.x * 32] = 0;
}

__global__ void f2h_kernel(const float* __restrict__ in, __half* __restrict__ o,
                           int n8) {
    int i = blockIdx.x * 256 + threadIdx.x;
    if (i < n8) {
        float4 a = ((const float4*)in)[2*i];
        float4 b = ((const float4*)in)[2*i+1];
        uint4 v;
        v.x = h2u(__floats2half2_rn(a.x, a.y));
        v.y = h2u(__floats2half2_rn(a.z, a.w));
        v.z = h2u(__floats2half2_rn(b.x, b.y));
        v.w = h2u(__floats2half2_rn(b.z, b.w));
        ((uint4*)o)[i] = v;
    }
}

// ---------------------------------------------------------------------------
// gi0 = x(fp16)@Wih0(fp16)^T + b1 + b2.   (R9 GEMM, unchanged)
#define GH_SMEM (1024 + 65536)
__global__ __launch_bounds__(256, 2) void gemm_h(
    const __half* __restrict__ A, const __half* __restrict__ B,
    const float* __restrict__ b1, const float* __restrict__ b2,
    float* __restrict__ C)
{
    extern __shared__ char sm_[];
    const uint32_t base = (smem_u32(sm_) + 1023) & ~1023u;
    const int tid = threadIdx.x, wid = tid >> 5, lane = tid & 31;
    const int nb = blockIdx.x * 128, mb = blockIdx.y * 128;
    const int wm = wid >> 2, wn = wid & 3;

    const int lrow = tid >> 1;
    const int ls0  = (tid & 1) * 4;
    const char* asrc0 = (const char*)(A + (size_t)(mb + lrow) * 1024);
    const char* bsrc0 = (const char*)(B + (size_t)(nb + lrow) * 1024);

    float acc[4][4][4];
#pragma unroll
    for (int i = 0; i < 4; i++)
#pragma unroll
        for (int j = 0; j < 4; j++)
#pragma unroll
            for (int q = 0; q < 4; q++) acc[i][j][q] = 0.f;

    const int lr = lane & 7, lg = lane >> 3;
    const int arow = lr + ((lg & 1) << 3), aksel = lg >> 1;
    const int brow = lr + ((lg >> 1) << 3), bksel = lg & 1;

#pragma unroll
    for (int i = 0; i < 4; i++) {
        int s = ls0 + i;
        cp_async16(base + SW128(lrow * 128 + s * 16), asrc0 + s * 16);
        cp_async16(base + 16384 + SW128(lrow * 128 + s * 16), bsrc0 + s * 16);
    }
    cp_commit();

    for (int c = 0; c < 16; c++) {
        if (c < 15) {
            uint32_t ab = base + ((c + 1) & 1) * 32768;
#pragma unroll
            for (int i = 0; i < 4; i++) {
                int s = ls0 + i;
                cp_async16(ab + SW128(lrow * 128 + s * 16),
                           asrc0 + (c + 1) * 128 + s * 16);
                cp_async16(ab + 16384 + SW128(lrow * 128 + s * 16),
                           bsrc0 + (c + 1) * 128 + s * 16);
            }
            cp_commit();
            cp_wait<1>();
        } else {
            cp_wait<0>();
        }
        __syncthreads();
        uint32_t ab = base + (c & 1) * 32768;
        uint32_t bb = ab + 16384;
#pragma unroll
        for (int ks = 0; ks < 4; ks++) {
            uint32_t afr[4][4], bfr[2][4];
#pragma unroll
            for (int mf = 0; mf < 4; mf++)
                ldm4(afr[mf], ab + SW128((wm * 64 + mf * 16 + arow) * 128
                                         + (ks * 2 + aksel) * 16));
#pragma unroll
            for (int bh = 0; bh < 2; bh++)
                ldm4(bfr[bh], bb + SW128((wn * 32 + bh * 16 + brow) * 128
                                         + (ks * 2 + bksel) * 16));
#pragma unroll
            for (int mf = 0; mf < 4; mf++)
#pragma unroll
                for (int nf = 0; nf < 4; nf++)
                    mma16816(acc[mf][nf], afr[mf], &bfr[nf >> 1][(nf & 1) * 2]);
        }
        __syncthreads();
    }

#pragma unroll
    for (int mf = 0; mf < 4; mf++) {
#pragma unroll
        for (int nf = 0; nf < 4; nf++) {
            int m = mb + wm * 64 + mf * 16 + (lane >> 2);
            int n = nb + wn * 32 + nf * 8 + 2 * (lane & 3);
            float bs0 = b1[n] + b2[n], bs1 = b1[n + 1] + b2[n + 1];
            float* cp0 = C + (size_t)m * 4096 + n;
            float* cp1 = cp0 + 8 * 4096;
            *(float2*)cp0 = make_float2(acc[mf][nf][0] + bs0, acc[mf][nf][1] + bs1);
            *(float2*)cp1 = make_float2(acc[mf][nf][2] + bs0, acc[mf][nf][3] + bs1);
        }
    }
}

// ---------------------------------------------------------------------------
// Merged two-layer dataflow recurrence.  128 CTAs = 64 col-groups x 2 batch
// halves; per super-step t: phase 1 = R9-exact layer-0 step t (Ab as ring-8),
// phase 2 = layer-1 step t-1 (gi1 + rec1 fused MMA; W_ih1/W_hh1 streamed).
// SMEM bytes from base:
//   Wb 0(131072) | Ab 131072(32768) | Y2 163840(8192) | H1R 172032(8192)
//   WI 180224(16384) | WH 196608(16384) | Gs 212992(8448)
#define R_SMEM (1024 + 221440 + 64)
__global__ __launch_bounds__(256) void lstm_merged(
    const float* __restrict__ Whh0, const float* __restrict__ gi,
    const float* __restrict__ bih1, const float* __restrict__ bhh1,
    float* __restrict__ out, int full)
{
    extern __shared__ char sm_[];
    const uint32_t base = (smem_u32(sm_) + 1023) & ~1023u;
    const uint32_t Wb = base, Ab = base + 131072;
    const uint32_t Y2 = base + 163840, H1R = base + 172032;
    const uint32_t WI = base + 180224, WH = base + 196608;
    float* Gs = (float*)(sm_ + (base + 212992 - smem_u32(sm_)));
    const int tid = threadIdx.x, wid = tid >> 5, lane = tid & 31;
    const int jb = blockIdx.x;
    const int cg = jb >> 1;            // col-group 0..63 (16 h-cols)
    const int bs = jb & 1;             // batch half

    // ---- Whh0 slice -> fp16 SMEM (resident): 64 gate cols x 1024 k --------
#pragma unroll 2
    for (int it = 0; it < 32; it++) {
        int idx = tid + it * 256;
        int lc = idx >> 7;
        int k8 = (idx & 127) * 8;
        int grow = ((lc >> 4) << 10) + cg * 16 + (lc & 15);
        const float* wp = Whh0 + (size_t)grow * 1024 + k8;
        float4 u = *(const float4*)wp;
        float4 v = *(const float4*)(wp + 4);
        sts128(Wb + (k8 >> 6) * 8192 + SW128(lc * 128 + (k8 & 63) * 2),
               h2u(__floats2half2_rn(u.x, u.y)), h2u(__floats2half2_rn(u.z, u.w)),
               h2u(__floats2half2_rn(v.x, v.y)), h2u(__floats2half2_rn(v.z, v.w)));
    }
    __syncthreads();

    const int wn = wid, n0 = wn * 8;
    const int lr = lane & 7, lg = lane >> 3;
    const int arow = lr + ((lg & 1) << 3), aksel = lg >> 1;
    const int bnr = lane & 7, bksel = (lane >> 3) & 1;
    const int srow = tid >> 3, sseg = tid & 7;

    const int bl = tid >> 3;           // batch local 0..31
    const int jl0 = (tid & 7) * 2;     // col pair base
    float c0reg[2] = {0.f, 0.f};
    float c1reg[2] = {0.f, 0.f};

    // layer-1 bias (b_ih1 + b_hh1) for this thread's 2 cells x 4 gates
    float bsum1[4][2];
#pragma unroll
    for (int g = 0; g < 4; g++)
#pragma unroll
        for (int e = 0; e < 2; e++) {
            int j = (g << 10) + cg * 16 + jl0 + e;
            bsum1[g][e] = bih1[j] + bhh1[j];
        }

    const __half* wih1 = g_wh + (size_t)G4 * HID;
    volatile int* f0 = g_flags;
    volatile int* f1 = g_flags + NCTA * 32;

    for (int t = 0; t <= SEQ; t++) {
        // ======================= phase 1: layer-0 step t ====================
        if (t < SEQ) {
            const float* gp = gi + (size_t)t * BG
                            + (size_t)(bs * 32 + bl) * 4096 + cg * 16 + jl0;
            float2 ggv[4];
#pragma unroll
            for (int g = 0; g < 4; g++) ggv[g] = *(const float2*)(gp + (g << 10));

            if (t > 0) {
                const char* hp = (const char*)(g_h16 + (size_t)(t - 1) * BH);
#pragma unroll
                for (int g = 0; g < 2; g++) {
                    if (tid < 16)
                        poll_ge((const int*)&f0[((g * 16 + tid) * 2 + bs) * 32], t);
                    else if (g == 0 && tid >= 32 && tid < 96 && t >= 2)
                        poll_ge((const int*)&f1[((tid - 32) * 2 + bs) * 32], t - 1);
                    __syncthreads();
#pragma unroll
                    for (int cc = 0; cc < 4; cc++) {
                        int c = g * 4 + cc;
                        cp_async16(Ab + (c & 7) * 4096 + SW128(srow * 128 + sseg * 16),
                                   hp + (size_t)(bs * 32 + srow) * 2048 + c * 128 + sseg * 16);
                    }
                    cp_commit();
                }
                float acc[2][4];
#pragma unroll
                for (int f = 0; f < 2; f++)
#pragma unroll
                    for (int q = 0; q < 4; q++) acc[f][q] = 0.f;

#pragma unroll
                for (int g = 0; g < 4; g++) {
                    if (g < 3) cp_wait<1>(); else cp_wait<0>();
                    __syncthreads();
#pragma unroll
                    for (int cc = 0; cc < 4; cc++) {
                        int c = g * 4 + cc;
                        uint32_t wbase = Wb + c * 8192;
                        uint32_t abase = Ab + (c & 7) * 4096;
#pragma unroll
                        for (int ks = 0; ks < 4; ks++) {
                            uint32_t af0[4], af1[4], bf[2];
                            ldm4(af0, abase + SW128(arow * 128 + (ks * 2 + aksel) * 16));
                            ldm4(af1, abase + SW128((16 + arow) * 128 + (ks * 2 + aksel) * 16));
                            ldm2(bf, wbase + SW128((n0 + bnr) * 128 + (ks * 2 + bksel) * 16));
                            mma16816(acc[0], af0, bf);
                            mma16816(acc[1], af1, bf);
                        }
                    }
                    if (g + 2 < 4) {
                        int gn = g + 2;
                        if (tid < 16)
                            poll_ge((const int*)&f0[((gn * 16 + tid) * 2 + bs) * 32], t);
                        __syncthreads();
#pragma unroll
                        for (int cc = 0; cc < 4; cc++) {
                            int c = gn * 4 + cc;
                            cp_async16(Ab + (c & 7) * 4096 + SW128(srow * 128 + sseg * 16),
                                       hp + (size_t)(bs * 32 + srow) * 2048 + c * 128 + sseg * 16);
                        }
                        cp_commit();
                    }
                }
                {   // gate exchange
                    int bf0 = lane >> 2;
                    int lc = n0 + 2 * (lane & 3);
#pragma unroll
                    for (int f = 0; f < 2; f++) {
                        int b = f * 16 + bf0;
                        Gs[lc * 33 + b]           = acc[f][0];
                        Gs[(lc + 1) * 33 + b]     = acc[f][1];
                        Gs[lc * 33 + b + 8]       = acc[f][2];
                        Gs[(lc + 1) * 33 + b + 8] = acc[f][3];
                    }
                }
                __syncthreads();
            }
            // cell update layer-0
            float hv2[2];
#pragma unroll
            for (int e = 0; e < 2; e++) {
                int jl = jl0 + e;
                float i_g = (e ? ggv[0].y : ggv[0].x);
                float f_g = (e ? ggv[1].y : ggv[1].x);
                float g_g = (e ? ggv[2].y : ggv[2].x);
                float o_g = (e ? ggv[3].y : ggv[3].x);
                if (t > 0) {
                    i_g += Gs[(0 * 16 + jl) * 33 + bl];
                    f_g += Gs[(1 * 16 + jl) * 33 + bl];
                    g_g += Gs[(2 * 16 + jl) * 33 + bl];
                    o_g += Gs[(3 * 16 + jl) * 33 + bl];
                }
                float cn = sigm(f_g) * c0reg[e] + sigm(i_g) * tanh_f(g_g);
                c0reg[e] = cn;
                hv2[e] = sigm(o_g) * tanh_f(cn);
            }
            size_t off = (size_t)t * BH + (size_t)(bs * 32 + bl) * 1024 + cg * 16 + jl0;
            *(uint32_t*)(g_h16 + off) = h2u(__floats2half2_rn(hv2[0], hv2[1]));
            __threadfence();
            __syncthreads();
            if (tid == 0)
                asm volatile("st.release.gpu.global.b32 [%0], %1;"
                             :: "l"((int*)&f0[jb * 32]), "r"(t + 1) : "memory");
            if (t == SEQ - 1 && full) {
                size_t tail = (size_t)(bs * 32 + bl) * 1024 + cg * 16 + jl0;
                *(float2*)(out + HOFF + tail) = make_float2(hv2[0], hv2[1]);
                *(float2*)(out + COFF + tail) = make_float2(c0reg[0], c0reg[1]);
            }
        } else {
            // t == SEQ stub: ensure y0(511) + h1(510) fully published
            if (tid < 64)       poll_ge((const int*)&f0[(tid * 2 + bs) * 32], SEQ);
            else if (tid < 128) poll_ge((const int*)&f1[((tid - 64) * 2 + bs) * 32], SEQ - 1);
            __syncthreads();
        }

        // ======================= phase 2: layer-1 step t-1 ==================
        if (t >= 1) {
            const int t1 = t - 1;
            const bool rec = (t >= 2);
            const char* hpy = (const char*)(g_h16 + (size_t)t1 * BH);
            const char* hp1 = rec ? (const char*)(g_h1 + (size_t)(t - 2) * BH) : hpy;

            auto issue2 = [&](int c) {
                int s = c & 1;
                cp_async16(Y2 + s * 4096 + SW128(srow * 128 + sseg * 16),
                           hpy + (size_t)(bs * 32 + srow) * 2048 + c * 128 + sseg * 16);
                if (rec)
                    cp_async16(H1R + s * 4096 + SW128(srow * 128 + sseg * 16),
                               hp1 + (size_t)(bs * 32 + srow) * 2048 + c * 128 + sseg * 16);
#pragma unroll
                for (int q = 0; q < 2; q++) {
                    int idx = tid + q * 256;
                    int lc = idx >> 3, seg = idx & 7;
                    int grow = ((lc >> 4) << 10) + cg * 16 + (lc & 15);
                    cp_async16(WI + s * 8192 + SW128(lc * 128 + seg * 16),
                               (const char*)(wih1 + (size_t)grow * 1024) + c * 128 + seg * 16);
                    if (rec)
                        cp_async16(WH + s * 8192 + SW128(lc * 128 + seg * 16),
                                   (const char*)(g_whh1h + (size_t)grow * 1024) + c * 128 + seg * 16);
                }
                cp_commit();
            };

            float acc1[2][4];
#pragma unroll
            for (int f = 0; f < 2; f++)
#pragma unroll
                for (int q = 0; q < 4; q++) acc1[f][q] = 0.f;

            issue2(0);
            issue2(1);
            for (int c = 0; c < 16; c++) {
                if (c < 15) cp_wait<1>(); else cp_wait<0>();
                __syncthreads();
                int s = c & 1;
#pragma unroll
                for (int ks = 0; ks < 4; ks++) {
                    uint32_t ay0[4], ay1[4], b0[2];
                    ldm4(ay0, Y2 + s * 4096 + SW128(arow * 128 + (ks * 2 + aksel) * 16));
                    ldm4(ay1, Y2 + s * 4096 + SW128((16 + arow) * 128 + (ks * 2 + aksel) * 16));
                    ldm2(b0, WI + s * 8192 + SW128((n0 + bnr) * 128 + (ks * 2 + bksel) * 16));
                    mma16816(acc1[0], ay0, b0);
                    mma16816(acc1[1], ay1, b0);
                    if (rec) {
                        uint32_t ah0[4], ah1[4], b1r[2];
                        ldm4(ah0, H1R + s * 4096 + SW128(arow * 128 + (ks * 2 + aksel) * 16));
                        ldm4(ah1, H1R + s * 4096 + SW128((16 + arow) * 128 + (ks * 2 + aksel) * 16));
                        ldm2(b1r, WH + s * 8192 + SW128((n0 + bnr) * 128 + (ks * 2 + bksel) * 16));
                        mma16816(acc1[0], ah0, b1r);
                        mma16816(acc1[1], ah1, b1r);
                    }
                }
                __syncthreads();
                if (c + 2 < 16) issue2(c + 2);
            }
            {   // gate exchange (Gs reuse; last reads were before phase-1's bar)
                int bf0 = lane >> 2;
                int lc = n0 + 2 * (lane & 3);
#pragma unroll
                for (int f = 0; f < 2; f++) {
                    int b = f * 16 + bf0;
                    Gs[lc * 33 + b]           = acc1[f][0];
                    Gs[(lc + 1) * 33 + b]     = acc1[f][1];
                    Gs[lc * 33 + b + 8]       = acc1[f][2];
                    Gs[(lc + 1) * 33 + b + 8] = acc1[f][3];
                }
            }
            __syncthreads();
            float hv2[2];
#pragma unroll
            for (int e = 0; e < 2; e++) {
                int jl = jl0 + e;
                float i_g = Gs[(0 * 16 + jl) * 33 + bl] + bsum1[0][e];
                float f_g = Gs[(1 * 16 + jl) * 33 + bl] + bsum1[1][e];
                float g_g = Gs[(2 * 16 + jl) * 33 + bl] + bsum1[2][e];
                float o_g = Gs[(3 * 16 + jl) * 33 + bl] + bsum1[3][e];
                float cn = sigm(f_g) * c1reg[e] + sigm(i_g) * tanh_f(g_g);
                c1reg[e] = cn;
                hv2[e] = sigm(o_g) * tanh_f(cn);
            }
            size_t off = (size_t)t1 * BH + (size_t)(bs * 32 + bl) * 1024 + cg * 16 + jl0;
            *(uint32_t*)(g_h1 + off) = h2u(__floats2half2_rn(hv2[0], hv2[1]));
            __threadfence();
            __syncthreads();
            if (tid == 0 && t < SEQ)
                asm volatile("st.release.gpu.global.b32 [%0], %1;"
                             :: "l"((int*)&f1[jb * 32]), "r"(t) : "memory");
            *(float2*)(out + off) = make_float2(hv2[0], hv2[1]);   // y1 fp32
            if (t == SEQ && full) {
                size_t tail = (size_t)BH + (size_t)(bs * 32 + bl) * 1024 + cg * 16 + jl0;
                *(float2*)(out + HOFF + tail) = make_float2(hv2[0], hv2[1]);
                *(float2*)(out + COFF + tail) = make_float2(c1reg[0], c1reg[1]);
            }
        }
    }
}

// ---------------------------------------------------------------------------
extern "C" void kernel_launch(void* const* d_in, const int* in_sizes, int n_in,
                              void* d_out, int out_size)
{
    const float* x    = (const float*)d_in[0];
    const float* wih0 = (const float*)d_in[1];
    const float* whh0 = (const float*)d_in[2];
    const float* bih0 = (const float*)d_in[3];
    const float* bhh0 = (const float*)d_in[4];
    const float* wih1 = (const float*)d_in[5];
    const float* whh1 = (const float*)d_in[6];
    const float* bih1 = (const float*)d_in[7];
    const float* bhh1 = (const float*)d_in[8];
    float* out = (float*)d_out;

    float *gi; __half *xh, *wh, *whh1h;
    cudaGetSymbolAddress((void**)&gi,    g_gi);
    cudaGetSymbolAddress((void**)&xh,    g_xh);
    cudaGetSymbolAddress((void**)&wh,    g_wh);
    cudaGetSymbolAddress((void**)&whh1h, g_whh1h);

    cudaFuncSetAttribute(gemm_h,      cudaFuncAttributeMaxDynamicSharedMemorySize, GH_SMEM);
    cudaFuncSetAttribute(lstm_merged, cudaFuncAttributeMaxDynamicSharedMemorySize, R_SMEM);

    const int full = (out_size >= (int)(YSZ + 4 * BH)) ? 1 : 0;
    dim3 gg(32, 256);
    const int WN8 = G4 * HID / 8;

    f2h_kernel<<<(SEQ * BH / 8 + 255) / 256, 256>>>(x, xh, SEQ * BH / 8);
    f2h_kernel<<<(WN8 + 255) / 256, 256>>>(wih0, wh, WN8);
    f2h_kernel<<<(WN8 + 255) / 256, 256>>>(wih1, wh + (size_t)G4 * HID, WN8);
    f2h_kernel<<<(WN8 + 255) / 256, 256>>>(whh1, whh1h, WN8);
    reset_flags_kernel<<<1, 256>>>();

    gemm_h<<<gg, 256, GH_SMEM>>>(xh, wh, bih0, bhh0, gi);
    lstm_merged<<<NCTA, 256, R_SMEM>>>(whh0, gi, bih1, bhh1, out, full);
}

// round 16
// speedup vs baseline: 1.3914x; 1.0772x over previous
#include <cuda_runtime.h>
#include <cuda_fp16.h>
#include <cstdint>

#define SEQ 512
#define BATCH 64
#define HID 1024
#define G4 4096
#define BH (BATCH*HID)
#define BG (BATCH*G4)
#define YSZ (SEQ*BH)
#define HOFF YSZ
#define COFF (YSZ+2*BH)
#define NCTA 128

__device__ __align__(16) float  g_gi[SEQ*BG];     // input projections (fp32)
__device__ __align__(16) __half g_xh[SEQ*BH];     // x in fp16
__device__ __align__(16) __half g_h16[SEQ*BH];    // h stream fp16 (per layer)
__device__ __align__(16) __half g_wh[2*G4*HID];   // W_ih fp16, both layers
__device__ int g_flags[2*NCTA*32];                // per-layer per-CTA progress flags

// ---------------- helpers ---------------------------------------------------
__device__ __forceinline__ uint32_t smem_u32(const void* p) {
    uint32_t a;
    asm("{ .reg .u64 t; cvta.to.shared.u64 t, %1; cvt.u32.u64 %0, t; }"
        : "=r"(a) : "l"(p));
    return a;
}
#define SW128(x) ((x) ^ (((x) >> 3) & 0x70))

__device__ __forceinline__ void cp_async16(uint32_t dst, const void* src) {
    asm volatile("cp.async.cg.shared.global [%0], [%1], 16;" :: "r"(dst), "l"(src));
}
__device__ __forceinline__ void cp_commit() {
    asm volatile("cp.async.commit_group;");
}
template <int N> __device__ __forceinline__ void cp_wait() {
    asm volatile("cp.async.wait_group %0;" :: "n"(N));
}
__device__ __forceinline__ void sts128(uint32_t a, uint32_t x, uint32_t y,
                                       uint32_t z, uint32_t w) {
    asm volatile("st.shared.v4.b32 [%0], {%1,%2,%3,%4};"
                 :: "r"(a), "r"(x), "r"(y), "r"(z), "r"(w) : "memory");
}
__device__ __forceinline__ void ldm4(uint32_t* r, uint32_t a) {
    asm volatile("ldmatrix.sync.aligned.m8n8.x4.shared.b16 {%0,%1,%2,%3}, [%4];"
                 : "=r"(r[0]), "=r"(r[1]), "=r"(r[2]), "=r"(r[3]) : "r"(a));
}
__device__ __forceinline__ void ldm2(uint32_t* r, uint32_t a) {
    asm volatile("ldmatrix.sync.aligned.m8n8.x2.shared.b16 {%0,%1}, [%2];"
                 : "=r"(r[0]), "=r"(r[1]) : "r"(a));
}
__device__ __forceinline__ void mma16816(float* c, const uint32_t* a,
                                         const uint32_t* b) {
    asm volatile(
        "mma.sync.aligned.m16n8k16.row.col.f32.f16.f16.f32 "
        "{%0,%1,%2,%3}, {%4,%5,%6,%7}, {%8,%9}, {%0,%1,%2,%3};"
        : "+f"(c[0]), "+f"(c[1]), "+f"(c[2]), "+f"(c[3])
        : "r"(a[0]), "r"(a[1]), "r"(a[2]), "r"(a[3]), "r"(b[0]), "r"(b[1]));
}
__device__ __forceinline__ float sigm(float x)   { return 1.f / (1.f + __expf(-x)); }
__device__ __forceinline__ float tanh_f(float x) { return 1.f - 2.f / (__expf(2.f*x) + 1.f); }
__device__ __forceinline__ uint32_t h2u(__half2 h) { return *(uint32_t*)&h; }

// ---------------------------------------------------------------------------
__global__ void reset_flags_kernel() {
    if (threadIdx.x < 2 * NCTA) g_flags[threadIdx.x * 32] = 0;
}

__global__ void f2h_kernel(const float* __restrict__ in, __half* __restrict__ o,
                           int n8) {
    int i = blockIdx.x * 256 + threadIdx.x;
    if (i < n8) {
        float4 a = ((const float4*)in)[2*i];
        float4 b = ((const float4*)in)[2*i+1];
        uint4 v;
        v.x = h2u(__floats2half2_rn(a.x, a.y));
        v.y = h2u(__floats2half2_rn(a.z, a.w));
        v.z = h2u(__floats2half2_rn(b.x, b.y));
        v.w = h2u(__floats2half2_rn(b.z, b.w));
        ((uint4*)o)[i] = v;
    }
}

// ---------------------------------------------------------------------------
// gi = A(fp16)@B(fp16)^T + b1 + b2.  M=32768,N=4096,K=1024. (R9-exact)
#define GH_SMEM (1024 + 65536)
__global__ __launch_bounds__(256, 2) void gemm_h(
    const __half* __restrict__ A, const __half* __restrict__ B,
    const float* __restrict__ b1, const float* __restrict__ b2,
    float* __restrict__ C)
{
    extern __shared__ char sm_[];
    const uint32_t base = (smem_u32(sm_) + 1023) & ~1023u;
    const int tid = threadIdx.x, wid = tid >> 5, lane = tid & 31;
    const int nb = blockIdx.x * 128, mb = blockIdx.y * 128;
    const int wm = wid >> 2, wn = wid & 3;

    const int lrow = tid >> 1;
    const int ls0  = (tid & 1) * 4;
    const char* asrc0 = (const char*)(A + (size_t)(mb + lrow) * 1024);
    const char* bsrc0 = (const char*)(B + (size_t)(nb + lrow) * 1024);

    float acc[4][4][4];
#pragma unroll
    for (int i = 0; i < 4; i++)
#pragma unroll
        for (int j = 0; j < 4; j++)
#pragma unroll
            for (int q = 0; q < 4; q++) acc[i][j][q] = 0.f;

    const int lr = lane & 7, lg = lane >> 3;
    const int arow = lr + ((lg & 1) << 3), aksel = lg >> 1;
    const int brow = lr + ((lg >> 1) << 3), bksel = lg & 1;

#pragma unroll
    for (int i = 0; i < 4; i++) {
        int s = ls0 + i;
        cp_async16(base + SW128(lrow * 128 + s * 16), asrc0 + s * 16);
        cp_async16(base + 16384 + SW128(lrow * 128 + s * 16), bsrc0 + s * 16);
    }
    cp_commit();

    for (int c = 0; c < 16; c++) {
        if (c < 15) {
            uint32_t ab = base + ((c + 1) & 1) * 32768;
#pragma unroll
            for (int i = 0; i < 4; i++) {
                int s = ls0 + i;
                cp_async16(ab + SW128(lrow * 128 + s * 16),
                           asrc0 + (c + 1) * 128 + s * 16);
                cp_async16(ab + 16384 + SW128(lrow * 128 + s * 16),
                           bsrc0 + (c + 1) * 128 + s * 16);
            }
            cp_commit();
            cp_wait<1>();
        } else {
            cp_wait<0>();
        }
        __syncthreads();
        uint32_t ab = base + (c & 1) * 32768;
        uint32_t bb = ab + 16384;
#pragma unroll
        for (int ks = 0; ks < 4; ks++) {
            uint32_t afr[4][4], bfr[2][4];
#pragma unroll
            for (int mf = 0; mf < 4; mf++)
                ldm4(afr[mf], ab + SW128((wm * 64 + mf * 16 + arow) * 128
                                         + (ks * 2 + aksel) * 16));
#pragma unroll
            for (int bh = 0; bh < 2; bh++)
                ldm4(bfr[bh], bb + SW128((wn * 32 + bh * 16 + brow) * 128
                                         + (ks * 2 + bksel) * 16));
#pragma unroll
            for (int mf = 0; mf < 4; mf++)
#pragma unroll
                for (int nf = 0; nf < 4; nf++)
                    mma16816(acc[mf][nf], afr[mf], &bfr[nf >> 1][(nf & 1) * 2]);
        }
        __syncthreads();
    }

#pragma unroll
    for (int mf = 0; mf < 4; mf++) {
#pragma unroll
        for (int nf = 0; nf < 4; nf++) {
            int m = mb + wm * 64 + mf * 16 + (lane >> 2);
            int n = nb + wn * 32 + nf * 8 + 2 * (lane & 3);
            float bs0 = b1[n] + b2[n], bs1 = b1[n + 1] + b2[n + 1];
            float* cp0 = C + (size_t)m * 4096 + n;
            float* cp1 = cp0 + 8 * 4096;
            *(float2*)cp0 = make_float2(acc[mf][nf][0] + bs0, acc[mf][nf][1] + bs1);
            *(float2*)cp1 = make_float2(acc[mf][nf][2] + bs0, acc[mf][nf][3] + bs1);
        }
    }
}

// ---------------------------------------------------------------------------
// R9-exact dataflow recurrence. 128 CTAs = 64 col-groups x 2 batch halves.
// Fixed group order, plain acquire spins, all-thread fence + tid0 release.
// Only delta vs R9: flag base is per-layer (no mid-graph resets needed).
#define R_SMEM (1024 + 131072 + 65536 + 8448)
__global__ __launch_bounds__(256) void lstm_df(
    const float* __restrict__ Whh, const float* __restrict__ gi,
    __half* __restrict__ h16, float* __restrict__ yout,
    float* __restrict__ out, int layer, int full)
{
    extern __shared__ char sm_[];
    const uint32_t base = (smem_u32(sm_) + 1023) & ~1023u;
    const uint32_t Wb = base, Ab = base + 131072, GsB = base + 196608;
    float* Gs = (float*)(sm_ + (GsB - smem_u32(sm_)));
    const int tid = threadIdx.x, wid = tid >> 5, lane = tid & 31;
    const int jb = blockIdx.x;
    const int cg = jb >> 1;            // col-group 0..63
    const int bs = jb & 1;             // batch half 0..1
    int* flags = g_flags + layer * NCTA * 32;

    // ---- W_hh slice -> fp16 SMEM: 64 cols x 1024 k, 16 chunks of 64k ----
#pragma unroll 2
    for (int it = 0; it < 32; it++) {
        int idx = tid + it * 256;
        int lc = idx >> 7;
        int k8 = (idx & 127) * 8;
        int grow = ((lc >> 4) << 10) + cg * 16 + (lc & 15);
        const float* wp = Whh + (size_t)grow * 1024 + k8;
        float4 u = *(const float4*)wp;
        float4 v = *(const float4*)(wp + 4);
        sts128(Wb + (k8 >> 6) * 8192 + SW128(lc * 128 + (k8 & 63) * 2),
               h2u(__floats2half2_rn(u.x, u.y)), h2u(__floats2half2_rn(u.z, u.w)),
               h2u(__floats2half2_rn(v.x, v.y)), h2u(__floats2half2_rn(v.z, v.w)));
    }
    __syncthreads();

    const int wn = wid;
    const int n0 = wn * 8;
    const int lr = lane & 7, lg = lane >> 3;
    const int arow = lr + ((lg & 1) << 3), aksel = lg >> 1;
    const int bnr = lane & 7, bksel = (lane >> 3) & 1;
    const int srow = tid >> 3, sseg = tid & 7;

    const int bl = tid >> 3;
    const int jl0 = (tid & 7) * 2;
    float creg2[2] = {0.f, 0.f};

    for (int t = 0; t < SEQ; t++) {
        const float* gp = gi + (size_t)t * BG
                        + (size_t)(bs * 32 + bl) * 4096 + cg * 16 + jl0;
        float2 ggv[4];
#pragma unroll
        for (int g = 0; g < 4; g++) ggv[g] = *(const float2*)(gp + (g << 10));

        if (t > 0) {
            const char* hp = (const char*)(h16 + (size_t)(t - 1) * BH);
            // prologue: poll+issue groups 0,1 (fixed order)
#pragma unroll
            for (int g = 0; g < 2; g++) {
                if (tid < 16) {
                    const int* fp = (const int*)&flags[((g * 16 + tid) * 2 + bs) * 32];
                    int v;
                    do {
                        asm volatile("ld.acquire.gpu.global.b32 %0, [%1];"
                                     : "=r"(v) : "l"(fp));
                    } while (v < t);
                }
                __syncthreads();
#pragma unroll
                for (int cc = 0; cc < 4; cc++) {
                    int c = g * 4 + cc;
                    cp_async16(Ab + c * 4096 + SW128(srow * 128 + sseg * 16),
                               hp + (size_t)(bs * 32 + srow) * 2048 + c * 128 + sseg * 16);
                }
                cp_commit();
            }
            float acc[2][4];
#pragma unroll
            for (int f = 0; f < 2; f++)
#pragma unroll
                for (int q = 0; q < 4; q++) acc[f][q] = 0.f;

#pragma unroll
            for (int g = 0; g < 4; g++) {
                if (g < 3) cp_wait<1>(); else cp_wait<0>();
                __syncthreads();
#pragma unroll
                for (int cc = 0; cc < 4; cc++) {
                    int c = g * 4 + cc;
                    uint32_t wbase = Wb + c * 8192, abase = Ab + c * 4096;
#pragma unroll
                    for (int ks = 0; ks < 4; ks++) {
                        uint32_t af0[4], af1[4], bf[2];
                        ldm4(af0, abase + SW128(arow * 128 + (ks * 2 + aksel) * 16));
                        ldm4(af1, abase + SW128((16 + arow) * 128 + (ks * 2 + aksel) * 16));
                        ldm2(bf, wbase + SW128((n0 + bnr) * 128 + (ks * 2 + bksel) * 16));
                        mma16816(acc[0], af0, bf);
                        mma16816(acc[1], af1, bf);
                    }
                }
                if (g + 2 < 4) {
                    int gn = g + 2;
                    if (tid < 16) {
                        const int* fp = (const int*)&flags[((gn * 16 + tid) * 2 + bs) * 32];
                        int v;
                        do {
                            asm volatile("ld.acquire.gpu.global.b32 %0, [%1];"
                                         : "=r"(v) : "l"(fp));
                        } while (v < t);
                    }
                    __syncthreads();
#pragma unroll
                    for (int cc = 0; cc < 4; cc++) {
                        int c = gn * 4 + cc;
                        cp_async16(Ab + c * 4096 + SW128(srow * 128 + sseg * 16),
                                   hp + (size_t)(bs * 32 + srow) * 2048 + c * 128 + sseg * 16);
                    }
                    cp_commit();
                }
            }
            // gate exchange: Gs[lc][b] (stride 33)
            {
                int bf0 = lane >> 2;
                int lc = n0 + 2 * (lane & 3);
#pragma unroll
                for (int f = 0; f < 2; f++) {
                    int b = f * 16 + bf0;
                    Gs[lc * 33 + b]            = acc[f][0];
                    Gs[(lc + 1) * 33 + b]      = acc[f][1];
                    Gs[lc * 33 + b + 8]        = acc[f][2];
                    Gs[(lc + 1) * 33 + b + 8]  = acc[f][3];
                }
            }
            __syncthreads();
        }

        // ---- cell update: 256 threads x 2 cells ----
        float hv2[2];
#pragma unroll
        for (int e = 0; e < 2; e++) {
            int jl = jl0 + e;
            float i_g = (e ? ggv[0].y : ggv[0].x);
            float f_g = (e ? ggv[1].y : ggv[1].x);
            float g_g = (e ? ggv[2].y : ggv[2].x);
            float o_g = (e ? ggv[3].y : ggv[3].x);
            if (t > 0) {
                i_g += Gs[(0 * 16 + jl) * 33 + bl];
                f_g += Gs[(1 * 16 + jl) * 33 + bl];
                g_g += Gs[(2 * 16 + jl) * 33 + bl];
                o_g += Gs[(3 * 16 + jl) * 33 + bl];
            }
            float cn = sigm(f_g) * creg2[e] + sigm(i_g) * tanh_f(g_g);
            creg2[e] = cn;
            hv2[e] = sigm(o_g) * tanh_f(cn);
        }
        size_t off = (size_t)t * BH + (size_t)(bs * 32 + bl) * 1024 + cg * 16 + jl0;
        *(uint32_t*)(h16 + off) = h2u(__floats2half2_rn(hv2[0], hv2[1]));
        if (yout) {
            *(float2*)(yout + off) = make_float2(hv2[0], hv2[1]);
        }
        if (t == SEQ - 1 && full) {
            size_t tail = (size_t)layer * BH
                        + (size_t)(bs * 32 + bl) * 1024 + cg * 16 + jl0;
            *(float2*)(out + HOFF + tail) = make_float2(hv2[0], hv2[1]);
            *(float2*)(out + COFF + tail) = make_float2(creg2[0], creg2[1]);
        }
        // publish h(t): CTA-wide order via fence+bar, tid0 release (R9-exact)
        __threadfence();
        __syncthreads();
        if (tid == 0 && t < SEQ - 1)
            asm volatile("st.release.gpu.global.b32 [%0], %1;"
                         :: "l"(&flags[jb * 32]), "r"(t + 1) : "memory");
    }
}

// ---------------------------------------------------------------------------
extern "C" void kernel_launch(void* const* d_in, const int* in_sizes, int n_in,
                              void* d_out, int out_size)
{
    const float* x    = (const float*)d_in[0];
    const float* wih0 = (const float*)d_in[1];
    const float* whh0 = (const float*)d_in[2];
    const float* bih0 = (const float*)d_in[3];
    const float* bhh0 = (const float*)d_in[4];
    const float* wih1 = (const float*)d_in[5];
    const float* whh1 = (const float*)d_in[6];
    const float* bih1 = (const float*)d_in[7];
    const float* bhh1 = (const float*)d_in[8];
    float* out = (float*)d_out;

    float *gi; __half *xh, *h16, *wh;
    cudaGetSymbolAddress((void**)&gi,  g_gi);
    cudaGetSymbolAddress((void**)&xh,  g_xh);
    cudaGetSymbolAddress((void**)&h16, g_h16);
    cudaGetSymbolAddress((void**)&wh,  g_wh);

    cudaFuncSetAttribute(gemm_h,  cudaFuncAttributeMaxDynamicSharedMemorySize, GH_SMEM);
    cudaFuncSetAttribute(lstm_df, cudaFuncAttributeMaxDynamicSharedMemorySize, R_SMEM);

    const int full = (out_size >= (int)(YSZ + 4 * BH)) ? 1 : 0;
    dim3 gg(32, 256);
    const int WN8 = G4 * HID / 8;

    // all prologue work up front: one reset + three conversions
    reset_flags_kernel<<<1, 256>>>();
    f2h_kernel<<<(SEQ * BH / 8 + 255) / 256, 256>>>(x, xh, SEQ * BH / 8);
    f2h_kernel<<<(WN8 + 255) / 256, 256>>>(wih0, wh, WN8);
    f2h_kernel<<<(WN8 + 255) / 256, 256>>>(wih1, wh + (size_t)G4 * HID, WN8);

    // Layer 0
    gemm_h<<<gg, 256, GH_SMEM>>>(xh, wh, bih0, bhh0, gi);
    lstm_df<<<NCTA, 256, R_SMEM>>>(whh0, gi, h16, (float*)0, out, 0, full);
    // Layer 1 (GEMM A operand = layer-0 h16 stream; no reset needed)
    gemm_h<<<gg, 256, GH_SMEM>>>(h16, wh + (size_t)G4 * HID, bih1, bhh1, gi);
    lstm_df<<<NCTA, 256, R_SMEM>>>(whh1, gi, h16, out, out, 1, full);
}